// round 4
// baseline (speedup 1.0000x reference)
#include <cuda_runtime.h>
#include <cstddef>

#define NUM_CLASSES 1000000
#define FEAT_DIM    128
#define BATCH       16384
#define ALPHA       0.5f

#define N_ELEMS   ((size_t)NUM_CLASSES * FEAT_DIM)   // 128,000,000
#define N_QUADS   (N_ELEMS / 4)                       // 32,000,000

// Scratch: per-class partial sums (only rows for labels in the batch are ever
// touched), per-class counts, and a double loss accumulator.
__device__ float  g_sums[N_ELEMS];      // 512 MB static bss
__device__ float  g_counts[NUM_CLASSES];
__device__ double g_loss;

// ---------------------------------------------------------------------------
// K0: zero the scratch rows we will touch. One warp per batch element,
// lane k zeroes quad k of the class row (float4 stores).
// Duplicate labels race on writing 0 — benign.
// ---------------------------------------------------------------------------
__global__ void k_init(const int* __restrict__ labels)
{
    const int gid  = blockIdx.x * blockDim.x + threadIdx.x;
    const int w    = gid >> 5;          // batch element
    const int lane = gid & 31;
    if (w < BATCH) {
        const int l = labels[w];
        reinterpret_cast<float4*>(g_sums)[(size_t)l * 32 + lane] =
            make_float4(0.f, 0.f, 0.f, 0.f);
        if (lane == 0) g_counts[l] = 0.0f;
    }
    if (gid == 0) g_loss = 0.0;
}

// ---------------------------------------------------------------------------
// K1: scatter features into per-class sums + counts, accumulate loss.
// One warp per batch element; lane k owns feature quad k.
// ---------------------------------------------------------------------------
__global__ void k_accum(const float* __restrict__ features,
                        const float* __restrict__ centers,
                        const int*   __restrict__ labels)
{
    const int gid  = blockIdx.x * blockDim.x + threadIdx.x;
    const int w    = gid >> 5;
    const int lane = gid & 31;
    if (w >= BATCH) return;

    const int l = labels[w];
    const float4 f = reinterpret_cast<const float4*>(features)[(size_t)w * 32 + lane];
    const float4 c = reinterpret_cast<const float4*>(centers )[(size_t)l * 32 + lane];

    float* srow = g_sums + (size_t)l * FEAT_DIM + lane * 4;
    atomicAdd(srow + 0, f.x);
    atomicAdd(srow + 1, f.y);
    atomicAdd(srow + 2, f.z);
    atomicAdd(srow + 3, f.w);
    if (lane == 0) atomicAdd(&g_counts[l], 1.0f);

    const float dx = f.x - c.x, dy = f.y - c.y, dz = f.z - c.z, dw = f.w - c.w;
    float v = dx * dx + dy * dy + dz * dz + dw * dw;
    #pragma unroll
    for (int o = 16; o > 0; o >>= 1)
        v += __shfl_down_sync(0xffffffffu, v, o);
    if (lane == 0) atomicAdd(&g_loss, (double)v);
}

// ---------------------------------------------------------------------------
// K2 (fused copy + update): out[1 + i] = updated(centers[i]) with dst-ALIGNED
// float4 stores. Thread j produces out quad j = upd{c[4j-1], c[4j..4j+2]};
// the straddle element comes from the warp neighbor via shfl (lane 0 does one
// scalar load, L2-hot from the adjacent warp's line).
//
// Update rule applied inline for "present" classes (count > 0):
//   new = (1-ALPHA)*c + (ALPHA/cnt)*sum
// Quad elements 4j..4j+2 share class clsB = j/32 (rows are 128 elems = 32
// quads); straddle elem 4j-1 has class clsA = (4j-1)/128 (== clsB except at
// row boundaries). g_counts loads are warp-uniform -> broadcast sectors.
// Present-class path fires for ~0.002% of quads.
//
// Thread 0 writes the head out[1..3], the tail out[N], and the loss out[0].
// ---------------------------------------------------------------------------
__global__ void k_copy_upd(const float* __restrict__ c, float* __restrict__ out)
{
    const size_t j = (size_t)blockIdx.x * blockDim.x + threadIdx.x;  // dst quad
    float4 b = reinterpret_cast<const float4*>(c)[j];

    float pw = __shfl_up_sync(0xffffffffu, b.w, 1);
    if ((threadIdx.x & 31) == 0 && j > 0)
        pw = c[4 * j - 1];

    const int clsB = (int)(j >> 5);                 // class of elems 4j..4j+2
    const int clsA = (int)((4 * j - 1) >> 7);       // class of straddle elem
    const float cntB = g_counts[clsB];
    const float cntA = (clsA == clsB) ? cntB : g_counts[clsA];

    if (cntA > 0.0f && j > 0) {                     // update straddle element
        const float k2 = ALPHA / cntA;
        pw = (1.0f - ALPHA) * pw + k2 * g_sums[4 * j - 1];
    }
    if (cntB > 0.0f) {                              // update body elements
        const float k2 = ALPHA / cntB;
        const float4 s = reinterpret_cast<const float4*>(g_sums)[j];
        b.x = (1.0f - ALPHA) * b.x + k2 * s.x;
        b.y = (1.0f - ALPHA) * b.y + k2 * s.y;
        b.z = (1.0f - ALPHA) * b.z + k2 * s.z;
        b.w = (1.0f - ALPHA) * b.w + k2 * s.w;      // b.w used by j==0 head? no: head uses x,y,z only
    }

    if (j == 0) {
        out[0] = (float)(g_loss / (2.0 * (double)BATCH));
        out[1] = b.x; out[2] = b.y; out[3] = b.z;
        // tail element c[N-1], class NUM_CLASSES-1
        float tail = c[N_ELEMS - 1];
        const float cntT = g_counts[NUM_CLASSES - 1];
        if (cntT > 0.0f)
            tail = (1.0f - ALPHA) * tail + (ALPHA / cntT) * g_sums[N_ELEMS - 1];
        out[N_ELEMS] = tail;
    } else {
        reinterpret_cast<float4*>(out)[j] = make_float4(pw, b.x, b.y, b.z);
    }
}

// ---------------------------------------------------------------------------
extern "C" void kernel_launch(void* const* d_in, const int* in_sizes, int n_in,
                              void* d_out, int out_size)
{
    const float* features = (const float*)d_in[0];
    const float* centers  = (const float*)d_in[1];
    const int*   labels   = (const int*)d_in[2];
    float*       out      = (float*)d_out;

    (void)in_sizes; (void)n_in; (void)out_size;

    const int warps_grid = (BATCH * 32) / 256;          // 2048 blocks of 256

    k_init    <<<warps_grid, 256>>>(labels);
    k_accum   <<<warps_grid, 256>>>(features, centers, labels);
    k_copy_upd<<<(int)(N_QUADS / 256), 256>>>(centers, out);   // 125,000 blocks
}

// round 5
// speedup vs baseline: 1.0284x; 1.0284x over previous
#include <cuda_runtime.h>
#include <cstddef>

#define NUM_CLASSES 1000000
#define FEAT_DIM    128
#define BATCH       16384
#define ALPHA       0.5f

#define N_ELEMS   ((size_t)NUM_CLASSES * FEAT_DIM)   // 128,000,000
#define N_QUADS   (N_ELEMS / 4)                       // 32,000,000

// Scratch. .bss => zero-initialized at load. Each graph replay leaves these
// zeroed again (clean-on-exit in k_update), so no init kernel is needed.
__device__ float  g_sums[N_ELEMS];      // 512 MB static bss
__device__ float  g_counts[NUM_CLASSES];
__device__ int    g_owner[BATCH];       // 1 if batch elem is unique owner of its label
__device__ double g_loss;

// ---------------------------------------------------------------------------
// K1: scatter features into per-class sums + counts, accumulate loss, and
// elect one owner warp per distinct label (first atomicAdd on the count).
// One warp per batch element; lane k owns feature quad k.
// ---------------------------------------------------------------------------
__global__ void k_accum(const float* __restrict__ features,
                        const float* __restrict__ centers,
                        const int*   __restrict__ labels)
{
    const int gid  = blockIdx.x * blockDim.x + threadIdx.x;
    const int w    = gid >> 5;
    const int lane = gid & 31;
    if (w >= BATCH) return;

    const int l = labels[w];
    const float4 f = reinterpret_cast<const float4*>(features)[(size_t)w * 32 + lane];
    const float4 c = reinterpret_cast<const float4*>(centers )[(size_t)l * 32 + lane];

    float* srow = g_sums + (size_t)l * FEAT_DIM + lane * 4;
    atomicAdd(srow + 0, f.x);
    atomicAdd(srow + 1, f.y);
    atomicAdd(srow + 2, f.z);
    atomicAdd(srow + 3, f.w);
    if (lane == 0) {
        const float old = atomicAdd(&g_counts[l], 1.0f);
        g_owner[w] = (old == 0.0f) ? 1 : 0;   // unique owner of label l
    }

    const float dx = f.x - c.x, dy = f.y - c.y, dz = f.z - c.z, dw = f.w - c.w;
    float v = dx * dx + dy * dy + dz * dz + dw * dw;
    #pragma unroll
    for (int o = 16; o > 0; o >>= 1)
        v += __shfl_down_sync(0xffffffffu, v, o);
    if (lane == 0) atomicAdd(&g_loss, (double)v);
}

// ---------------------------------------------------------------------------
// K2: PURE bulk shifted copy  out[1 + i] = centers[i]  with dst-ALIGNED
// float4 stores. Thread j produces out quad j = {c[4j-1], c[4j..4j+2]};
// the straddle element comes from the warp neighbor via shfl_up (lane 0
// scalar-loads it, L2-hot from the adjacent warp's line). No sparse logic
// here — keeping the stream pure is worth ~18 us vs the fused variant.
// Thread 0 writes the head out[1..3] and the tail out[N].
// ---------------------------------------------------------------------------
__global__ void k_copy(const float* __restrict__ c, float* __restrict__ out)
{
    const size_t j = (size_t)blockIdx.x * blockDim.x + threadIdx.x;  // dst quad
    const float4 b = reinterpret_cast<const float4*>(c)[j];

    float pw = __shfl_up_sync(0xffffffffu, b.w, 1);
    if ((threadIdx.x & 31) == 0 && j > 0)
        pw = c[4 * j - 1];

    if (j == 0) {
        out[1] = b.x; out[2] = b.y; out[3] = b.z;
        out[N_ELEMS] = c[N_ELEMS - 1];               // tail element
    } else {
        reinterpret_cast<float4*>(out)[j] = make_float4(pw, b.x, b.y, b.z);
    }
}

// ---------------------------------------------------------------------------
// K3: owner warps overwrite their class row with the momentum update, then
// CLEAR the scratch they consumed (sums row, count, owner flag) so the next
// graph replay starts from zeroed state. Thread 0 emits the loss and zeroes
// the accumulator. Non-owner (duplicate-label) warps do nothing — the owner
// writes the identical row.
//   new_c = (1-ALPHA)*c + (ALPHA/cnt)*sum
// ---------------------------------------------------------------------------
__global__ void k_update(const float* __restrict__ centers,
                         const int*   __restrict__ labels,
                         float*       __restrict__ out)
{
    const int gid  = blockIdx.x * blockDim.x + threadIdx.x;
    const int w    = gid >> 5;
    const int lane = gid & 31;

    if (gid == 0) {
        out[0] = (float)(g_loss / (2.0 * (double)BATCH));
        g_loss = 0.0;
    }
    if (w >= BATCH) return;
    if (!g_owner[w]) return;                 // warp-uniform branch

    const int l = labels[w];
    const float cnt = g_counts[l];
    const float k1  = 1.0f - ALPHA;
    const float k2  = ALPHA / fmaxf(cnt, 1.0f);

    const size_t q = (size_t)l * 32 + lane;
    const float4 c = reinterpret_cast<const float4*>(centers)[q];
    const float4 s = reinterpret_cast<const float4*>(g_sums)[q];

    float* o = out + 1 + (size_t)l * FEAT_DIM + lane * 4;  // misaligned: scalar stores
    o[0] = k1 * c.x + k2 * s.x;
    o[1] = k1 * c.y + k2 * s.y;
    o[2] = k1 * c.z + k2 * s.z;
    o[3] = k1 * c.w + k2 * s.w;

    // clean-on-exit: restore zeroed scratch for the next replay
    reinterpret_cast<float4*>(g_sums)[q] = make_float4(0.f, 0.f, 0.f, 0.f);
    if (lane == 0) {
        g_counts[l] = 0.0f;
        g_owner[w]  = 0;
    }
}

// ---------------------------------------------------------------------------
extern "C" void kernel_launch(void* const* d_in, const int* in_sizes, int n_in,
                              void* d_out, int out_size)
{
    const float* features = (const float*)d_in[0];
    const float* centers  = (const float*)d_in[1];
    const int*   labels   = (const int*)d_in[2];
    float*       out      = (float*)d_out;

    (void)in_sizes; (void)n_in; (void)out_size;

    const int warps_grid = (BATCH * 32) / 256;          // 2048 blocks of 256

    k_accum <<<warps_grid, 256>>>(features, centers, labels);
    k_copy  <<<(int)(N_QUADS / 256), 256>>>(centers, out);   // 125,000 blocks
    k_update<<<warps_grid, 256>>>(centers, labels, out);
}